// round 1
// baseline (speedup 1.0000x reference)
#include <cuda_runtime.h>
#include <math.h>

#define BATCH 2048
#define HDIM  4096
#define NHEAD 4
#define HSZ   1024

typedef unsigned long long ull;

// ---------------- scratch (device globals; no runtime allocation) ----------
__device__ float g_xn  [(size_t)BATCH * HDIM];
__device__ float g_xact[(size_t)BATCH * HDIM];
__device__ float g_gates[4ull * BATCH * HDIM];   // i, f, z, o pre-activations

// ---------------- helpers ---------------------------------------------------
__device__ __forceinline__ float warpSum(float v) {
#pragma unroll
    for (int o = 16; o > 0; o >>= 1) v += __shfl_down_sync(0xffffffffu, v, o);
    return v;
}

__device__ __forceinline__ ull pack_dup(float a) {
    ull r; unsigned ai = __float_as_uint(a);
    asm("mov.b64 %0, {%1, %1};" : "=l"(r) : "r"(ai));
    return r;
}
__device__ __forceinline__ ull fma2(ull a, ull b, ull c) {
    ull d;
    asm("fma.rn.f32x2 %0, %1, %2, %3;" : "=l"(d) : "l"(a), "l"(b), "l"(c));
    return d;
}

// ---------------- Kernel A: layernorm + conv + silu + new_conv_state -------
__global__ __launch_bounds__(256) void ln_conv_kernel(
    const float* __restrict__ x, const float* __restrict__ cs,
    const float* __restrict__ ln_w, const float* __restrict__ conv_w,
    const float* __restrict__ conv_b, float* __restrict__ out_ncs)
{
    const int b   = blockIdx.x;
    const int tid = threadIdx.x;
    const float* xr = x + (size_t)b * HDIM;

    float4 xv[4];
    float s = 0.f, sq = 0.f;
#pragma unroll
    for (int i = 0; i < 4; i++) {
        xv[i] = *(const float4*)(xr + (size_t)(tid + i * 256) * 4);
        s  += xv[i].x + xv[i].y + xv[i].z + xv[i].w;
        sq += xv[i].x * xv[i].x + xv[i].y * xv[i].y + xv[i].z * xv[i].z + xv[i].w * xv[i].w;
    }
    __shared__ float rs[8], rq[8];
    float ws = warpSum(s), wq = warpSum(sq);
    if ((tid & 31) == 0) { rs[tid >> 5] = ws; rq[tid >> 5] = wq; }
    __syncthreads();
    float ts = 0.f, tq = 0.f;
#pragma unroll
    for (int i = 0; i < 8; i++) { ts += rs[i]; tq += rq[i]; }
    const float mean = ts * (1.f / HDIM);
    const float var  = tq * (1.f / HDIM) - mean * mean;
    const float rstd = rsqrtf(var + 1e-5f);

    const float* csb = cs      + (size_t)b * 3 * HDIM;
    float*       ncs = out_ncs + (size_t)b * 3 * HDIM;

#pragma unroll
    for (int i = 0; i < 4; i++) {
        const int c = (tid + i * 256) * 4;
        float4 lw = *(const float4*)(ln_w + c);
        float4 xn;
        xn.x = (xv[i].x - mean) * rstd * lw.x;
        xn.y = (xv[i].y - mean) * rstd * lw.y;
        xn.z = (xv[i].z - mean) * rstd * lw.z;
        xn.w = (xv[i].w - mean) * rstd * lw.w;

        float4 c0 = *(const float4*)(csb + c);
        float4 c1 = *(const float4*)(csb + HDIM + c);
        float4 c2 = *(const float4*)(csb + 2 * HDIM + c);
        float4 cb = *(const float4*)(conv_b + c);
        float4 w0 = *(const float4*)(conv_w + (size_t)(c + 0) * 4);
        float4 w1 = *(const float4*)(conv_w + (size_t)(c + 1) * 4);
        float4 w2 = *(const float4*)(conv_w + (size_t)(c + 2) * 4);
        float4 w3 = *(const float4*)(conv_w + (size_t)(c + 3) * 4);

        float4 xc;
        xc.x = c0.x * w0.x + c1.x * w0.y + c2.x * w0.z + xn.x * w0.w + cb.x;
        xc.y = c0.y * w1.x + c1.y * w1.y + c2.y * w1.z + xn.y * w1.w + cb.y;
        xc.z = c0.z * w2.x + c1.z * w2.y + c2.z * w2.z + xn.z * w2.w + cb.z;
        xc.w = c0.w * w3.x + c1.w * w3.y + c2.w * w3.z + xn.w * w3.w + cb.w;

        float4 xa;
        xa.x = xc.x / (1.f + expf(-xc.x));
        xa.y = xc.y / (1.f + expf(-xc.y));
        xa.z = xc.z / (1.f + expf(-xc.z));
        xa.w = xc.w / (1.f + expf(-xc.w));

        *(float4*)(g_xn   + (size_t)b * HDIM + c) = xn;
        *(float4*)(g_xact + (size_t)b * HDIM + c) = xa;
        *(float4*)(ncs + c)            = c1;
        *(float4*)(ncs + HDIM + c)     = c2;
        *(float4*)(ncs + 2 * HDIM + c) = xn;
    }
}

// ---------------- Kernel B: fused gate GEMMs (f32x2 packed FMA) ------------
#define BM 128
#define BN 128
#define BKK 16
#define SPAD 4

__global__ __launch_bounds__(256, 2) void gemm_kernel(
    const float* __restrict__ rec,
    const float* __restrict__ wi_in, const float* __restrict__ wf_in,
    const float* __restrict__ wz_in, const float* __restrict__ wo_in,
    const float* __restrict__ wi_st, const float* __restrict__ wf_st,
    const float* __restrict__ wz_st, const float* __restrict__ wo_st,
    const float* __restrict__ bi, const float* __restrict__ bf,
    const float* __restrict__ bz, const float* __restrict__ bo)
{
    const int combo = blockIdx.z;
    const int g = combo >> 2, n = combo & 3;

    const float* Win4[4]  = { wi_in, wf_in, wz_in, wo_in };
    const float* Wst4[4]  = { wi_st, wf_st, wz_st, wo_st };
    const float* bias4[4] = { bi, bf, bz, bo };

    const float* A1   = (g < 2 ? g_xact : g_xn) + n * HSZ;
    const float* A2   = rec + n * HSZ;
    const float* W1   = Win4[g] + (size_t)n * HSZ * HSZ;
    const float* W2   = Wst4[g] + (size_t)n * HSZ * HSZ;
    const float* bias = bias4[g] + n * HSZ;
    float* Cp = g_gates + (size_t)g * BATCH * HDIM + n * HSZ;

    const int m0 = blockIdx.y * BM;
    const int n0 = blockIdx.x * BN;

    __shared__ __align__(16) float As[BKK][BM + SPAD];
    __shared__ __align__(16) float Bs[BKK][BN + SPAD];

    const int tid = threadIdx.x;
    const int tx = tid & 15, ty = tid >> 4;

    ull acc[8][4];
#pragma unroll
    for (int r = 0; r < 8; r++)
#pragma unroll
        for (int j = 0; j < 4; j++) acc[r][j] = 0ull;   // == (0.f, 0.f)

#pragma unroll 1
    for (int pass = 0; pass < 2; ++pass) {
        const float* A = pass ? A2 : A1;
        const float* W = pass ? W2 : W1;
#pragma unroll 1
        for (int kt = 0; kt < HSZ; kt += BKK) {
#pragma unroll
            for (int i = 0; i < 2; ++i) {
                const int idx = tid + i * 256;
                const int r = idx >> 2, c4 = (idx & 3) * 4;
                float4 av = *(const float4*)(A + (size_t)(m0 + r) * HDIM + kt + c4);
                As[c4 + 0][r] = av.x; As[c4 + 1][r] = av.y;
                As[c4 + 2][r] = av.z; As[c4 + 3][r] = av.w;
                float4 wv = *(const float4*)(W + (size_t)(n0 + r) * HSZ + kt + c4);
                Bs[c4 + 0][r] = wv.x; Bs[c4 + 1][r] = wv.y;
                Bs[c4 + 2][r] = wv.z; Bs[c4 + 3][r] = wv.w;
            }
            __syncthreads();
#pragma unroll
            for (int k = 0; k < BKK; ++k) {
                float4 a0 = *(const float4*)&As[k][ty * 8];
                float4 a1 = *(const float4*)&As[k][ty * 8 + 4];
                ulonglong2 b0 = *(const ulonglong2*)&Bs[k][tx * 8];
                ulonglong2 b1 = *(const ulonglong2*)&Bs[k][tx * 8 + 4];
                float ar[8] = { a0.x, a0.y, a0.z, a0.w, a1.x, a1.y, a1.z, a1.w };
#pragma unroll
                for (int r = 0; r < 8; ++r) {
                    ull aa = pack_dup(ar[r]);
                    acc[r][0] = fma2(aa, b0.x, acc[r][0]);
                    acc[r][1] = fma2(aa, b0.y, acc[r][1]);
                    acc[r][2] = fma2(aa, b1.x, acc[r][2]);
                    acc[r][3] = fma2(aa, b1.y, acc[r][3]);
                }
            }
            __syncthreads();
        }
    }

    float4 bv0 = *(const float4*)(bias + n0 + tx * 8);
    float4 bv1 = *(const float4*)(bias + n0 + tx * 8 + 4);
    const float badd[8] = { bv0.x, bv0.y, bv0.z, bv0.w, bv1.x, bv1.y, bv1.z, bv1.w };

#pragma unroll
    for (int r = 0; r < 8; ++r) {
        const int row = m0 + ty * 8 + r;
        float o[8];
#pragma unroll
        for (int j = 0; j < 4; ++j) {
            union { ull u; float2 f; } cvt; cvt.u = acc[r][j];
            o[2 * j]     = cvt.f.x + badd[2 * j];
            o[2 * j + 1] = cvt.f.y + badd[2 * j + 1];
        }
        float* cp = Cp + (size_t)row * HDIM + n0 + tx * 8;
        *(float4*)cp       = make_float4(o[0], o[1], o[2], o[3]);
        *(float4*)(cp + 4) = make_float4(o[4], o[5], o[6], o[7]);
    }
}

// ---------------- Kernel C: gate math + group norm + outputs ---------------
__global__ __launch_bounds__(256) void gate_kernel(
    const float* __restrict__ x,      const float* __restrict__ cell,
    const float* __restrict__ normst, const float* __restrict__ maxst,
    const float* __restrict__ gn_w,   const float* __restrict__ gn_b,
    float* __restrict__ dout)
{
    const int blk = blockIdx.x;
    const int b = blk >> 2, n = blk & 3;
    const int tid = threadIdx.x;
    const size_t BH = (size_t)BATCH * HDIM;
    const size_t base = (size_t)b * HDIM + n * HSZ;
    const int c = tid * 4;

    float4 t;
    float iv[4], fv[4], zv[4], ov[4], cv[4], nv[4], mv[4];
    t = *(const float4*)(g_gates + 0 * BH + base + c); iv[0]=t.x; iv[1]=t.y; iv[2]=t.z; iv[3]=t.w;
    t = *(const float4*)(g_gates + 1 * BH + base + c); fv[0]=t.x; fv[1]=t.y; fv[2]=t.z; fv[3]=t.w;
    t = *(const float4*)(g_gates + 2 * BH + base + c); zv[0]=t.x; zv[1]=t.y; zv[2]=t.z; zv[3]=t.w;
    t = *(const float4*)(g_gates + 3 * BH + base + c); ov[0]=t.x; ov[1]=t.y; ov[2]=t.z; ov[3]=t.w;
    t = *(const float4*)(cell   + base + c); cv[0]=t.x; cv[1]=t.y; cv[2]=t.z; cv[3]=t.w;
    t = *(const float4*)(normst + base + c); nv[0]=t.x; nv[1]=t.y; nv[2]=t.z; nv[3]=t.w;
    t = *(const float4*)(maxst  + base + c); mv[0]=t.x; mv[1]=t.y; mv[2]=t.z; mv[3]=t.w;

    float y[4], cn[4], nn[4], mn[4];
    float s = 0.f, sq = 0.f;
#pragma unroll
    for (int j = 0; j < 4; ++j) {
        float fj  = fv[j];
        float lsf = fminf(fj, 0.f) - log1pf(expf(-fabsf(fj)));
        float lfm = mv[j] + lsf;
        float ij  = iv[j];
        float mnew = fmaxf(ij, lfm);
        float ig = expf(ij  - mnew);
        float fg = expf(lfm - mnew);
        float cnew = fg * cv[j] + ig * tanhf(zv[j]);
        float nnew = fg * nv[j] + ig;
        float so   = 1.f / (1.f + expf(-ov[j]));
        float yj   = so * cnew / (nnew + 1e-6f);
        y[j] = yj; cn[j] = cnew; nn[j] = nnew; mn[j] = mnew;
        s += yj; sq += yj * yj;
    }

    __shared__ float rs[8], rq[8];
    float ws = warpSum(s), wq = warpSum(sq);
    if ((tid & 31) == 0) { rs[tid >> 5] = ws; rq[tid >> 5] = wq; }
    __syncthreads();
    float ts = 0.f, tq = 0.f;
#pragma unroll
    for (int i = 0; i < 8; i++) { ts += rs[i]; tq += rq[i]; }
    const float mean = ts * (1.f / HSZ);
    const float var  = tq * (1.f / HSZ) - mean * mean;
    const float rstd = rsqrtf(var + 1e-5f);

    const int h = n * HSZ + c;
    float4 gw = *(const float4*)(gn_w + h);
    float4 gb = *(const float4*)(gn_b + h);
    float4 xs = *(const float4*)(x + base + c);
    const float gwv[4] = { gw.x, gw.y, gw.z, gw.w };
    const float gbv[4] = { gb.x, gb.y, gb.z, gb.w };
    const float xv4[4] = { xs.x, xs.y, xs.z, xs.w };

    float ot[4];
#pragma unroll
    for (int j = 0; j < 4; ++j)
        ot[j] = (y[j] - mean) * rstd * gwv[j] + gbv[j] + xv4[j];

    *(float4*)(dout + 0 * BH + base + c) = make_float4(ot[0], ot[1], ot[2], ot[3]);
    *(float4*)(dout + 4 * BH + base + c) = make_float4(y[0],  y[1],  y[2],  y[3]);
    *(float4*)(dout + 5 * BH + base + c) = make_float4(cn[0], cn[1], cn[2], cn[3]);
    *(float4*)(dout + 6 * BH + base + c) = make_float4(nn[0], nn[1], nn[2], nn[3]);
    *(float4*)(dout + 7 * BH + base + c) = make_float4(mn[0], mn[1], mn[2], mn[3]);
}

// ---------------- launch -----------------------------------------------------
extern "C" void kernel_launch(void* const* d_in, const int* in_sizes, int n_in,
                              void* d_out, int out_size)
{
    const float* x      = (const float*)d_in[0];
    const float* cs     = (const float*)d_in[1];
    const float* rec    = (const float*)d_in[2];
    const float* cell   = (const float*)d_in[3];
    const float* normst = (const float*)d_in[4];
    const float* maxst  = (const float*)d_in[5];
    const float* ln_w   = (const float*)d_in[6];
    const float* conv_w = (const float*)d_in[7];
    const float* conv_b = (const float*)d_in[8];
    const float* wi_in  = (const float*)d_in[9];
    const float* wf_in  = (const float*)d_in[10];
    const float* wz_in  = (const float*)d_in[11];
    const float* wo_in  = (const float*)d_in[12];
    const float* wi_st  = (const float*)d_in[13];
    const float* wf_st  = (const float*)d_in[14];
    const float* wz_st  = (const float*)d_in[15];
    const float* wo_st  = (const float*)d_in[16];
    const float* bi     = (const float*)d_in[17];
    const float* bf     = (const float*)d_in[18];
    const float* bz     = (const float*)d_in[19];
    const float* bo     = (const float*)d_in[20];
    const float* gn_w   = (const float*)d_in[21];
    const float* gn_b   = (const float*)d_in[22];
    float* out = (float*)d_out;

    // new_conv_state lives at offset B*H in d_out
    ln_conv_kernel<<<BATCH, 256>>>(x, cs, ln_w, conv_w, conv_b,
                                   out + (size_t)BATCH * HDIM);

    dim3 grid(HSZ / BN, BATCH / BM, 16);
    gemm_kernel<<<grid, 256>>>(rec,
                               wi_in, wf_in, wz_in, wo_in,
                               wi_st, wf_st, wz_st, wo_st,
                               bi, bf, bz, bo);

    gate_kernel<<<BATCH * NHEAD, 256>>>(x, cell, normst, maxst, gn_w, gn_b, out);
}

// round 3
// speedup vs baseline: 1.8972x; 1.8972x over previous
#include <cuda_runtime.h>
#include <cuda_bf16.h>
#include <math.h>
#include <stdint.h>

#define BATCH 2048
#define HDIM  4096
#define NHEAD 4
#define HSZ   1024

#define BM 128
#define BN 128
#define BK 32
#define NCHUNK 64          // 2 passes * (1024/32)

#define TSTRIDE 144        // bytes per smem tile row (32 bf16 = 64B data + pad)
#define TILE_B  (128 * TSTRIDE)          // 18432
#define STAGE_B (4 * TILE_B)             // Ah, Al, Bh, Bl
#define SMEM_B  (2 * STAGE_B)            // 147456

typedef __nv_bfloat16 bf16;

// ---------------- scratch (device globals; no runtime allocation) ----------
__device__ __align__(16) bf16 g_xn_hi  [(size_t)BATCH * HDIM];
__device__ __align__(16) bf16 g_xn_lo  [(size_t)BATCH * HDIM];
__device__ __align__(16) bf16 g_xact_hi[(size_t)BATCH * HDIM];
__device__ __align__(16) bf16 g_xact_lo[(size_t)BATCH * HDIM];
__device__ __align__(16) bf16 g_rec_hi [(size_t)BATCH * HDIM];
__device__ __align__(16) bf16 g_rec_lo [(size_t)BATCH * HDIM];
__device__ __align__(16) bf16 g_w_hi   [8ull * NHEAD * HSZ * HSZ];
__device__ __align__(16) bf16 g_w_lo   [8ull * NHEAD * HSZ * HSZ];
__device__ __align__(16) float g_gates [4ull * BATCH * HDIM];

// ---------------- helpers ---------------------------------------------------
__device__ __forceinline__ float warpSum(float v) {
#pragma unroll
    for (int o = 16; o > 0; o >>= 1) v += __shfl_down_sync(0xffffffffu, v, o);
    return v;
}

__device__ __forceinline__ uint32_t smem_u32(const void* p) {
    uint32_t a;
    asm("{ .reg .u64 t; cvta.to.shared.u64 t, %1; cvt.u32.u64 %0, t; }"
        : "=r"(a) : "l"(p));
    return a;
}

__device__ __forceinline__ void cp16(uint32_t saddr, const void* gaddr) {
    asm volatile("cp.async.cg.shared.global [%0], [%1], 16;"
                 :: "r"(saddr), "l"(gaddr));
}

__device__ __forceinline__ void ldsm4(uint32_t& r0, uint32_t& r1,
                                      uint32_t& r2, uint32_t& r3, uint32_t a) {
    asm volatile("ldmatrix.sync.aligned.m8n8.x4.shared.b16 {%0,%1,%2,%3}, [%4];"
                 : "=r"(r0), "=r"(r1), "=r"(r2), "=r"(r3) : "r"(a));
}

__device__ __forceinline__ void mma_bf16(float* c, const uint32_t* a,
                                         uint32_t b0, uint32_t b1) {
    asm volatile(
        "mma.sync.aligned.m16n8k16.row.col.f32.bf16.bf16.f32 "
        "{%0,%1,%2,%3}, {%4,%5,%6,%7}, {%8,%9}, {%0,%1,%2,%3};"
        : "+f"(c[0]), "+f"(c[1]), "+f"(c[2]), "+f"(c[3])
        : "r"(a[0]), "r"(a[1]), "r"(a[2]), "r"(a[3]), "r"(b0), "r"(b1));
}

__device__ __forceinline__ void split_bf16(float x, bf16& h, bf16& l) {
    h = __float2bfloat16(x);
    l = __float2bfloat16(x - __bfloat162float(h));
}

// ---------------- Kernel A: layernorm + conv + silu + hi/lo emit -----------
__global__ __launch_bounds__(256) void ln_conv_kernel(
    const float* __restrict__ x, const float* __restrict__ cs,
    const float* __restrict__ ln_w, const float* __restrict__ conv_w,
    const float* __restrict__ conv_b, float* __restrict__ out_ncs)
{
    const int b   = blockIdx.x;
    const int tid = threadIdx.x;
    const float* xr = x + (size_t)b * HDIM;

    float4 xv[4];
    float s = 0.f, sq = 0.f;
#pragma unroll
    for (int i = 0; i < 4; i++) {
        xv[i] = *(const float4*)(xr + (size_t)(tid + i * 256) * 4);
        s  += xv[i].x + xv[i].y + xv[i].z + xv[i].w;
        sq += xv[i].x * xv[i].x + xv[i].y * xv[i].y + xv[i].z * xv[i].z + xv[i].w * xv[i].w;
    }
    __shared__ float rs[8], rq[8];
    float ws = warpSum(s), wq = warpSum(sq);
    if ((tid & 31) == 0) { rs[tid >> 5] = ws; rq[tid >> 5] = wq; }
    __syncthreads();
    float ts = 0.f, tq = 0.f;
#pragma unroll
    for (int i = 0; i < 8; i++) { ts += rs[i]; tq += rq[i]; }
    const float mean = ts * (1.f / HDIM);
    const float var  = tq * (1.f / HDIM) - mean * mean;
    const float rstd = rsqrtf(var + 1e-5f);

    const float* csb = cs      + (size_t)b * 3 * HDIM;
    float*       ncs = out_ncs + (size_t)b * 3 * HDIM;

#pragma unroll
    for (int i = 0; i < 4; i++) {
        const int c = (tid + i * 256) * 4;
        float4 lw = *(const float4*)(ln_w + c);
        float4 xn;
        xn.x = (xv[i].x - mean) * rstd * lw.x;
        xn.y = (xv[i].y - mean) * rstd * lw.y;
        xn.z = (xv[i].z - mean) * rstd * lw.z;
        xn.w = (xv[i].w - mean) * rstd * lw.w;

        float4 c0 = *(const float4*)(csb + c);
        float4 c1 = *(const float4*)(csb + HDIM + c);
        float4 c2 = *(const float4*)(csb + 2 * HDIM + c);
        float4 cb = *(const float4*)(conv_b + c);
        float4 w0 = *(const float4*)(conv_w + (size_t)(c + 0) * 4);
        float4 w1 = *(const float4*)(conv_w + (size_t)(c + 1) * 4);
        float4 w2 = *(const float4*)(conv_w + (size_t)(c + 2) * 4);
        float4 w3 = *(const float4*)(conv_w + (size_t)(c + 3) * 4);

        float4 xc;
        xc.x = c0.x * w0.x + c1.x * w0.y + c2.x * w0.z + xn.x * w0.w + cb.x;
        xc.y = c0.y * w1.x + c1.y * w1.y + c2.y * w1.z + xn.y * w1.w + cb.y;
        xc.z = c0.z * w2.x + c1.z * w2.y + c2.z * w2.z + xn.z * w2.w + cb.z;
        xc.w = c0.w * w3.x + c1.w * w3.y + c2.w * w3.z + xn.w * w3.w + cb.w;

        float4 xa;
        xa.x = xc.x / (1.f + expf(-xc.x));
        xa.y = xc.y / (1.f + expf(-xc.y));
        xa.z = xc.z / (1.f + expf(-xc.z));
        xa.w = xc.w / (1.f + expf(-xc.w));

        union { bf16 bb[4]; uint2 u; } nh, nl, ah, al;
        split_bf16(xn.x, nh.bb[0], nl.bb[0]); split_bf16(xn.y, nh.bb[1], nl.bb[1]);
        split_bf16(xn.z, nh.bb[2], nl.bb[2]); split_bf16(xn.w, nh.bb[3], nl.bb[3]);
        split_bf16(xa.x, ah.bb[0], al.bb[0]); split_bf16(xa.y, ah.bb[1], al.bb[1]);
        split_bf16(xa.z, ah.bb[2], al.bb[2]); split_bf16(xa.w, ah.bb[3], al.bb[3]);

        const size_t off = (size_t)b * HDIM + c;
        *(uint2*)(g_xn_hi   + off) = nh.u;
        *(uint2*)(g_xn_lo   + off) = nl.u;
        *(uint2*)(g_xact_hi + off) = ah.u;
        *(uint2*)(g_xact_lo + off) = al.u;

        *(float4*)(ncs + c)            = c1;
        *(float4*)(ncs + HDIM + c)     = c2;
        *(float4*)(ncs + 2 * HDIM + c) = xn;
    }
}

// ---------------- conversion kernels ----------------------------------------
__global__ __launch_bounds__(256) void convert_w_kernel(
    const float* __restrict__ w0, const float* __restrict__ w1,
    const float* __restrict__ w2, const float* __restrict__ w3,
    const float* __restrict__ w4, const float* __restrict__ w5,
    const float* __restrict__ w6, const float* __restrict__ w7)
{
    const float* srcs[8] = { w0, w1, w2, w3, w4, w5, w6, w7 };
    const float* s = srcs[blockIdx.y];
    const size_t base4 = (size_t)blockIdx.y * (NHEAD * HSZ * (HSZ / 4));
    const int i = blockIdx.x * 256 + threadIdx.x;
    float4 v = ((const float4*)s)[i];
    union { bf16 bb[4]; uint2 u; } h, l;
    split_bf16(v.x, h.bb[0], l.bb[0]); split_bf16(v.y, h.bb[1], l.bb[1]);
    split_bf16(v.z, h.bb[2], l.bb[2]); split_bf16(v.w, h.bb[3], l.bb[3]);
    ((uint2*)g_w_hi)[base4 + i] = h.u;
    ((uint2*)g_w_lo)[base4 + i] = l.u;
}

__global__ __launch_bounds__(256) void convert_rec_kernel(const float* __restrict__ src)
{
    const int i = blockIdx.x * 256 + threadIdx.x;
    float4 v = ((const float4*)src)[i];
    union { bf16 bb[4]; uint2 u; } h, l;
    split_bf16(v.x, h.bb[0], l.bb[0]); split_bf16(v.y, h.bb[1], l.bb[1]);
    split_bf16(v.z, h.bb[2], l.bb[2]); split_bf16(v.w, h.bb[3], l.bb[3]);
    ((uint2*)g_rec_hi)[i] = h.u;
    ((uint2*)g_rec_lo)[i] = l.u;
}

// ---------------- Kernel B: HMMA bf16-split GEMM ---------------------------
__global__ __launch_bounds__(256, 1) void gemm_kernel(
    const float* __restrict__ bi, const float* __restrict__ bf_,
    const float* __restrict__ bz, const float* __restrict__ bo)
{
    extern __shared__ __align__(1024) char smem[];
    const uint32_t sbase = smem_u32(smem);
    const int tid  = threadIdx.x;
    const int wid  = tid >> 5;
    const int lane = tid & 31;

    const int g  = blockIdx.z >> 2;
    const int nh = blockIdx.z & 3;
    const int m0 = blockIdx.y * BM;
    const int n0 = blockIdx.x * BN;

    const bf16* aHi0 = (g < 2 ? g_xact_hi : g_xn_hi);
    const bf16* aLo0 = (g < 2 ? g_xact_lo : g_xn_lo);
    const size_t wb0 = ((size_t)g)       * NHEAD * HSZ * HSZ + (size_t)nh * HSZ * HSZ;
    const size_t wb1 = ((size_t)(g + 4)) * NHEAD * HSZ * HSZ + (size_t)nh * HSZ * HSZ;

    // loader indexing: thread -> (row, 32-byte half of the 64B row)
    const int lr = tid >> 1;
    const int cb = (tid & 1) * 32;          // smem byte offset within row
    const int ke = (tid & 1) * 16;          // gmem bf16-elem offset within 32-elem row

    // per-chunk load
    auto load_chunk = [&](int c) {
        const int pass = c >> 5;
        const int kt   = (c & 31) * BK;
        const uint32_t st = sbase + (c & 1) * STAGE_B;
        const bf16* aH = (pass ? g_rec_hi : aHi0);
        const bf16* aL = (pass ? g_rec_lo : aLo0);
        const bf16* wH = g_w_hi + (pass ? wb1 : wb0);
        const bf16* wL = g_w_lo + (pass ? wb1 : wb0);

        const size_t aoff = (size_t)(m0 + lr) * HDIM + (size_t)nh * HSZ + kt + ke;
        const size_t boff = (size_t)(n0 + lr) * HSZ + kt + ke;
        const uint32_t sdst = st + lr * TSTRIDE + cb;

        cp16(sdst,                 aH + aoff);
        cp16(sdst + 16,            aH + aoff + 8);
        cp16(sdst + TILE_B,        aL + aoff);
        cp16(sdst + TILE_B + 16,   aL + aoff + 8);
        cp16(sdst + 2 * TILE_B,      wH + boff);
        cp16(sdst + 2 * TILE_B + 16, wH + boff + 8);
        cp16(sdst + 3 * TILE_B,      wL + boff);
        cp16(sdst + 3 * TILE_B + 16, wL + boff + 8);
        asm volatile("cp.async.commit_group;");
    };

    // warp tiling: 4 warps along M (32 rows each), 2 along N (64 cols each)
    const int wm = wid & 3;
    const int wn = wid >> 2;

    const uint32_t aRowOff = (uint32_t)(wm * 32 + (lane & 15)) * TSTRIDE + ((lane >> 4) << 4);
    const uint32_t bRowOff = (uint32_t)(wn * 64 + (lane & 7) + ((lane >> 4) << 3)) * TSTRIDE
                             + (((lane >> 3) & 1) << 4);

    float acc[2][8][4];
#pragma unroll
    for (int mi = 0; mi < 2; mi++)
#pragma unroll
        for (int j = 0; j < 8; j++)
#pragma unroll
            for (int q = 0; q < 4; q++) acc[mi][j][q] = 0.f;

    load_chunk(0);

#pragma unroll 1
    for (int c = 0; c < NCHUNK; c++) {
        if (c + 1 < NCHUNK) {
            load_chunk(c + 1);
            asm volatile("cp.async.wait_group 1;");
        } else {
            asm volatile("cp.async.wait_group 0;");
        }
        __syncthreads();

        const uint32_t st = sbase + (c & 1) * STAGE_B;
#pragma unroll
        for (int kk = 0; kk < 2; kk++) {
            uint32_t ah0[4], ah1[4], al0[4], al1[4];
            const uint32_t ka = st + aRowOff + kk * 32;
            ldsm4(ah0[0], ah0[1], ah0[2], ah0[3], ka);
            ldsm4(ah1[0], ah1[1], ah1[2], ah1[3], ka + 16 * TSTRIDE);
            ldsm4(al0[0], al0[1], al0[2], al0[3], ka + TILE_B);
            ldsm4(al1[0], al1[1], al1[2], al1[3], ka + TILE_B + 16 * TSTRIDE);

#pragma unroll
            for (int jj = 0; jj < 4; jj++) {
                uint32_t bh[4], bl[4];
                const uint32_t kb = st + 2 * TILE_B + bRowOff + jj * 16 * TSTRIDE + kk * 32;
                ldsm4(bh[0], bh[1], bh[2], bh[3], kb);
                ldsm4(bl[0], bl[1], bl[2], bl[3], kb + TILE_B);

                const int j0 = jj * 2, j1 = jj * 2 + 1;
                // hi*hi
                mma_bf16(acc[0][j0], ah0, bh[0], bh[1]);
                mma_bf16(acc[1][j0], ah1, bh[0], bh[1]);
                mma_bf16(acc[0][j1], ah0, bh[2], bh[3]);
                mma_bf16(acc[1][j1], ah1, bh[2], bh[3]);
                // hi*lo
                mma_bf16(acc[0][j0], ah0, bl[0], bl[1]);
                mma_bf16(acc[1][j0], ah1, bl[0], bl[1]);
                mma_bf16(acc[0][j1], ah0, bl[2], bl[3]);
                mma_bf16(acc[1][j1], ah1, bl[2], bl[3]);
                // lo*hi
                mma_bf16(acc[0][j0], al0, bh[0], bh[1]);
                mma_bf16(acc[1][j0], al1, bh[0], bh[1]);
                mma_bf16(acc[0][j1], al0, bh[2], bh[3]);
                mma_bf16(acc[1][j1], al1, bh[2], bh[3]);
            }
        }
        __syncthreads();
    }

    // epilogue: add bias, write gates
    const float* bias = (g == 0) ? bi : (g == 1) ? bf_ : (g == 2) ? bz : bo;
    float* gbase = g_gates + (size_t)g * BATCH * HDIM;

#pragma unroll
    for (int mi = 0; mi < 2; mi++) {
        const int row0 = m0 + wm * 32 + mi * 16 + (lane >> 2);
#pragma unroll
        for (int j = 0; j < 8; j++) {
            const int col = n0 + wn * 64 + j * 8 + (lane & 3) * 2;
            const int h   = nh * HSZ + col;
            const float b0 = bias[h], b1 = bias[h + 1];
            float* p0 = gbase + (size_t)row0 * HDIM + h;
            float* p1 = p0 + 8 * HDIM;
            *(float2*)p0 = make_float2(acc[mi][j][0] + b0, acc[mi][j][1] + b1);
            *(float2*)p1 = make_float2(acc[mi][j][2] + b0, acc[mi][j][3] + b1);
        }
    }
}

// ---------------- Kernel C: gate math + group norm + outputs ---------------
__global__ __launch_bounds__(256) void gate_kernel(
    const float* __restrict__ x,      const float* __restrict__ cell,
    const float* __restrict__ normst, const float* __restrict__ maxst,
    const float* __restrict__ gn_w,   const float* __restrict__ gn_b,
    float* __restrict__ dout)
{
    const int blk = blockIdx.x;
    const int b = blk >> 2, n = blk & 3;
    const int tid = threadIdx.x;
    const size_t BH = (size_t)BATCH * HDIM;
    const size_t base = (size_t)b * HDIM + n * HSZ;
    const int c = tid * 4;

    float4 t;
    float iv[4], fv[4], zv[4], ov[4], cv[4], nv[4], mv[4];
    t = *(const float4*)(g_gates + 0 * BH + base + c); iv[0]=t.x; iv[1]=t.y; iv[2]=t.z; iv[3]=t.w;
    t = *(const float4*)(g_gates + 1 * BH + base + c); fv[0]=t.x; fv[1]=t.y; fv[2]=t.z; fv[3]=t.w;
    t = *(const float4*)(g_gates + 2 * BH + base + c); zv[0]=t.x; zv[1]=t.y; zv[2]=t.z; zv[3]=t.w;
    t = *(const float4*)(g_gates + 3 * BH + base + c); ov[0]=t.x; ov[1]=t.y; ov[2]=t.z; ov[3]=t.w;
    t = *(const float4*)(cell   + base + c); cv[0]=t.x; cv[1]=t.y; cv[2]=t.z; cv[3]=t.w;
    t = *(const float4*)(normst + base + c); nv[0]=t.x; nv[1]=t.y; nv[2]=t.z; nv[3]=t.w;
    t = *(const float4*)(maxst  + base + c); mv[0]=t.x; mv[1]=t.y; mv[2]=t.z; mv[3]=t.w;

    float y[4], cn[4], nn[4], mn[4];
    float s = 0.f, sq = 0.f;
#pragma unroll
    for (int j = 0; j < 4; ++j) {
        float fj  = fv[j];
        float lsf = fminf(fj, 0.f) - log1pf(expf(-fabsf(fj)));
        float lfm = mv[j] + lsf;
        float ij  = iv[j];
        float mnew = fmaxf(ij, lfm);
        float ig = expf(ij  - mnew);
        float fg = expf(lfm - mnew);
        float cnew = fg * cv[j] + ig * tanhf(zv[j]);
        float nnew = fg * nv[j] + ig;
        float so   = 1.f / (1.f + expf(-ov[j]));
        float yj   = so * cnew / (nnew + 1e-6f);
        y[j] = yj; cn[j] = cnew; nn[j] = nnew; mn[j] = mnew;
        s += yj; sq += yj * yj;
    }

    __shared__ float rs[8], rq[8];
    float ws = warpSum(s), wq = warpSum(sq);
    if ((tid & 31) == 0) { rs[tid >> 5] = ws; rq[tid >> 5] = wq; }
    __syncthreads();
    float ts = 0.f, tq = 0.f;
#pragma unroll
    for (int i = 0; i < 8; i++) { ts += rs[i]; tq += rq[i]; }
    const float mean = ts * (1.f / HSZ);
    const float var  = tq * (1.f / HSZ) - mean * mean;
    const float rstd = rsqrtf(var + 1e-5f);

    const int h = n * HSZ + c;
    float4 gw = *(const float4*)(gn_w + h);
    float4 gb = *(const float4*)(gn_b + h);
    float4 xs = *(const float4*)(x + base + c);
    const float gwv[4] = { gw.x, gw.y, gw.z, gw.w };
    const float gbv[4] = { gb.x, gb.y, gb.z, gb.w };
    const float xv4[4] = { xs.x, xs.y, xs.z, xs.w };

    float ot[4];
#pragma unroll
    for (int j = 0; j < 4; ++j)
        ot[j] = (y[j] - mean) * rstd * gwv[j] + gbv[j] + xv4[j];

    *(float4*)(dout + 0 * BH + base + c) = make_float4(ot[0], ot[1], ot[2], ot[3]);
    *(float4*)(dout + 4 * BH + base + c) = make_float4(y[0],  y[1],  y[2],  y[3]);
    *(float4*)(dout + 5 * BH + base + c) = make_float4(cn[0], cn[1], cn[2], cn[3]);
    *(float4*)(dout + 6 * BH + base + c) = make_float4(nn[0], nn[1], nn[2], nn[3]);
    *(float4*)(dout + 7 * BH + base + c) = make_float4(mn[0], mn[1], mn[2], mn[3]);
}

// ---------------- launch -----------------------------------------------------
extern "C" void kernel_launch(void* const* d_in, const int* in_sizes, int n_in,
                              void* d_out, int out_size)
{
    const float* x      = (const float*)d_in[0];
    const float* cs     = (const float*)d_in[1];
    const float* rec    = (const float*)d_in[2];
    const float* cell   = (const float*)d_in[3];
    const float* normst = (const float*)d_in[4];
    const float* maxst  = (const float*)d_in[5];
    const float* ln_w   = (const float*)d_in[6];
    const float* conv_w = (const float*)d_in[7];
    const float* conv_b = (const float*)d_in[8];
    const float* wi_in  = (const float*)d_in[9];
    const float* wf_in  = (const float*)d_in[10];
    const float* wz_in  = (const float*)d_in[11];
    const float* wo_in  = (const float*)d_in[12];
    const float* wi_st  = (const float*)d_in[13];
    const float* wf_st  = (const float*)d_in[14];
    const float* wz_st  = (const float*)d_in[15];
    const float* wo_st  = (const float*)d_in[16];
    const float* bi     = (const float*)d_in[17];
    const float* bf_    = (const float*)d_in[18];
    const float* bz     = (const float*)d_in[19];
    const float* bo     = (const float*)d_in[20];
    const float* gn_w   = (const float*)d_in[21];
    const float* gn_b   = (const float*)d_in[22];
    float* out = (float*)d_out;

    static int smem_set = 0;
    if (!smem_set) {
        cudaFuncSetAttribute(gemm_kernel, cudaFuncAttributeMaxDynamicSharedMemorySize,
                             SMEM_B);
        smem_set = 1;
    }

    ln_conv_kernel<<<BATCH, 256>>>(x, cs, ln_w, conv_w, conv_b,
                                   out + (size_t)BATCH * HDIM);

    convert_w_kernel<<<dim3(4096, 8), 256>>>(wi_in, wf_in, wz_in, wo_in,
                                             wi_st, wf_st, wz_st, wo_st);
    convert_rec_kernel<<<8192, 256>>>(rec);

    dim3 grid(HSZ / BN, BATCH / BM, 16);
    gemm_kernel<<<grid, 256, SMEM_B>>>(bi, bf_, bz, bo);

    gate_kernel<<<BATCH * NHEAD, 256>>>(x, cell, normst, maxst, gn_w, gn_b, out);
}

// round 4
// speedup vs baseline: 2.3489x; 1.2381x over previous
#include <cuda_runtime.h>
#include <cuda_bf16.h>
#include <math.h>
#include <stdint.h>

#define BATCH 2048
#define HDIM  4096
#define NHEAD 4
#define HSZ   1024

#define BM 128
#define BN 128
#define BK 64              // bf16 elems per K-chunk (128B data rows)
#define NCHUNK 32          // 2 passes * (1024/64)
#define NSTAGE 3

#define TSTRIDE 144        // 128B data + 16B pad; conflict-free for ldmatrix
#define TILE_B  (128 * TSTRIDE)          // 18432
#define STAGE_B (4 * TILE_B)             // Ah, Al, Bh, Bl = 73728
#define SMEM_B  (NSTAGE * STAGE_B)       // 221184

typedef __nv_bfloat16 bf16;

// ---------------- scratch (device globals; no runtime allocation) ----------
__device__ __align__(16) bf16 g_xn_hi  [(size_t)BATCH * HDIM];
__device__ __align__(16) bf16 g_xn_lo  [(size_t)BATCH * HDIM];
__device__ __align__(16) bf16 g_xact_hi[(size_t)BATCH * HDIM];
__device__ __align__(16) bf16 g_xact_lo[(size_t)BATCH * HDIM];
__device__ __align__(16) bf16 g_rec_hi [(size_t)BATCH * HDIM];
__device__ __align__(16) bf16 g_rec_lo [(size_t)BATCH * HDIM];
__device__ __align__(16) bf16 g_w_hi   [8ull * NHEAD * HSZ * HSZ];
__device__ __align__(16) bf16 g_w_lo   [8ull * NHEAD * HSZ * HSZ];
__device__ __align__(16) float g_gates [4ull * BATCH * HDIM];

// ---------------- helpers ---------------------------------------------------
__device__ __forceinline__ float warpSum(float v) {
#pragma unroll
    for (int o = 16; o > 0; o >>= 1) v += __shfl_down_sync(0xffffffffu, v, o);
    return v;
}

__device__ __forceinline__ uint32_t smem_u32(const void* p) {
    uint32_t a;
    asm("{ .reg .u64 t; cvta.to.shared.u64 t, %1; cvt.u32.u64 %0, t; }"
        : "=r"(a) : "l"(p));
    return a;
}

__device__ __forceinline__ void cp16(uint32_t saddr, const void* gaddr) {
    asm volatile("cp.async.cg.shared.global [%0], [%1], 16;"
                 :: "r"(saddr), "l"(gaddr));
}

__device__ __forceinline__ void ldsm4(uint32_t* r, uint32_t a) {
    asm volatile("ldmatrix.sync.aligned.m8n8.x4.shared.b16 {%0,%1,%2,%3}, [%4];"
                 : "=r"(r[0]), "=r"(r[1]), "=r"(r[2]), "=r"(r[3]) : "r"(a));
}

__device__ __forceinline__ void mma_bf16(float* c, const uint32_t* a,
                                         uint32_t b0, uint32_t b1) {
    asm volatile(
        "mma.sync.aligned.m16n8k16.row.col.f32.bf16.bf16.f32 "
        "{%0,%1,%2,%3}, {%4,%5,%6,%7}, {%8,%9}, {%0,%1,%2,%3};"
        : "+f"(c[0]), "+f"(c[1]), "+f"(c[2]), "+f"(c[3])
        : "r"(a[0]), "r"(a[1]), "r"(a[2]), "r"(a[3]), "r"(b0), "r"(b1));
}

__device__ __forceinline__ void split_bf16(float x, bf16& h, bf16& l) {
    h = __float2bfloat16(x);
    l = __float2bfloat16(x - __bfloat162float(h));
}

// ---------------- Kernel A: layernorm + conv + silu + hi/lo emit -----------
__global__ __launch_bounds__(256) void ln_conv_kernel(
    const float* __restrict__ x, const float* __restrict__ cs,
    const float* __restrict__ ln_w, const float* __restrict__ conv_w,
    const float* __restrict__ conv_b, float* __restrict__ out_ncs)
{
    const int b   = blockIdx.x;
    const int tid = threadIdx.x;
    const float* xr = x + (size_t)b * HDIM;

    float4 xv[4];
    float s = 0.f, sq = 0.f;
#pragma unroll
    for (int i = 0; i < 4; i++) {
        xv[i] = *(const float4*)(xr + (size_t)(tid + i * 256) * 4);
        s  += xv[i].x + xv[i].y + xv[i].z + xv[i].w;
        sq += xv[i].x * xv[i].x + xv[i].y * xv[i].y + xv[i].z * xv[i].z + xv[i].w * xv[i].w;
    }
    __shared__ float rs[8], rq[8];
    float ws = warpSum(s), wq = warpSum(sq);
    if ((tid & 31) == 0) { rs[tid >> 5] = ws; rq[tid >> 5] = wq; }
    __syncthreads();
    float ts = 0.f, tq = 0.f;
#pragma unroll
    for (int i = 0; i < 8; i++) { ts += rs[i]; tq += rq[i]; }
    const float mean = ts * (1.f / HDIM);
    const float var  = tq * (1.f / HDIM) - mean * mean;
    const float rstd = rsqrtf(var + 1e-5f);

    const float* csb = cs      + (size_t)b * 3 * HDIM;
    float*       ncs = out_ncs + (size_t)b * 3 * HDIM;

#pragma unroll
    for (int i = 0; i < 4; i++) {
        const int c = (tid + i * 256) * 4;
        float4 lw = *(const float4*)(ln_w + c);
        float4 xn;
        xn.x = (xv[i].x - mean) * rstd * lw.x;
        xn.y = (xv[i].y - mean) * rstd * lw.y;
        xn.z = (xv[i].z - mean) * rstd * lw.z;
        xn.w = (xv[i].w - mean) * rstd * lw.w;

        float4 c0 = *(const float4*)(csb + c);
        float4 c1 = *(const float4*)(csb + HDIM + c);
        float4 c2 = *(const float4*)(csb + 2 * HDIM + c);
        float4 cb = *(const float4*)(conv_b + c);
        float4 w0 = *(const float4*)(conv_w + (size_t)(c + 0) * 4);
        float4 w1 = *(const float4*)(conv_w + (size_t)(c + 1) * 4);
        float4 w2 = *(const float4*)(conv_w + (size_t)(c + 2) * 4);
        float4 w3 = *(const float4*)(conv_w + (size_t)(c + 3) * 4);

        float4 xc;
        xc.x = c0.x * w0.x + c1.x * w0.y + c2.x * w0.z + xn.x * w0.w + cb.x;
        xc.y = c0.y * w1.x + c1.y * w1.y + c2.y * w1.z + xn.y * w1.w + cb.y;
        xc.z = c0.z * w2.x + c1.z * w2.y + c2.z * w2.z + xn.z * w2.w + cb.z;
        xc.w = c0.w * w3.x + c1.w * w3.y + c2.w * w3.z + xn.w * w3.w + cb.w;

        float4 xa;
        xa.x = xc.x / (1.f + expf(-xc.x));
        xa.y = xc.y / (1.f + expf(-xc.y));
        xa.z = xc.z / (1.f + expf(-xc.z));
        xa.w = xc.w / (1.f + expf(-xc.w));

        union { bf16 bb[4]; uint2 u; } nh, nl, ah, al;
        split_bf16(xn.x, nh.bb[0], nl.bb[0]); split_bf16(xn.y, nh.bb[1], nl.bb[1]);
        split_bf16(xn.z, nh.bb[2], nl.bb[2]); split_bf16(xn.w, nh.bb[3], nl.bb[3]);
        split_bf16(xa.x, ah.bb[0], al.bb[0]); split_bf16(xa.y, ah.bb[1], al.bb[1]);
        split_bf16(xa.z, ah.bb[2], al.bb[2]); split_bf16(xa.w, ah.bb[3], al.bb[3]);

        const size_t off = (size_t)b * HDIM + c;
        *(uint2*)(g_xn_hi   + off) = nh.u;
        *(uint2*)(g_xn_lo   + off) = nl.u;
        *(uint2*)(g_xact_hi + off) = ah.u;
        *(uint2*)(g_xact_lo + off) = al.u;

        *(float4*)(ncs + c)            = c1;
        *(float4*)(ncs + HDIM + c)     = c2;
        *(float4*)(ncs + 2 * HDIM + c) = xn;
    }
}

// ---------------- conversion kernels ----------------------------------------
__global__ __launch_bounds__(256) void convert_w_kernel(
    const float* __restrict__ w0, const float* __restrict__ w1,
    const float* __restrict__ w2, const float* __restrict__ w3,
    const float* __restrict__ w4, const float* __restrict__ w5,
    const float* __restrict__ w6, const float* __restrict__ w7)
{
    const float* srcs[8] = { w0, w1, w2, w3, w4, w5, w6, w7 };
    const float* s = srcs[blockIdx.y];
    const size_t base4 = (size_t)blockIdx.y * (NHEAD * HSZ * (HSZ / 4));
    const int i = blockIdx.x * 256 + threadIdx.x;
    float4 v = ((const float4*)s)[i];
    union { bf16 bb[4]; uint2 u; } h, l;
    split_bf16(v.x, h.bb[0], l.bb[0]); split_bf16(v.y, h.bb[1], l.bb[1]);
    split_bf16(v.z, h.bb[2], l.bb[2]); split_bf16(v.w, h.bb[3], l.bb[3]);
    ((uint2*)g_w_hi)[base4 + i] = h.u;
    ((uint2*)g_w_lo)[base4 + i] = l.u;
}

__global__ __launch_bounds__(256) void convert_rec_kernel(const float* __restrict__ src)
{
    const int i = blockIdx.x * 256 + threadIdx.x;
    float4 v = ((const float4*)src)[i];
    union { bf16 bb[4]; uint2 u; } h, l;
    split_bf16(v.x, h.bb[0], l.bb[0]); split_bf16(v.y, h.bb[1], l.bb[1]);
    split_bf16(v.z, h.bb[2], l.bb[2]); split_bf16(v.w, h.bb[3], l.bb[3]);
    ((uint2*)g_rec_hi)[i] = h.u;
    ((uint2*)g_rec_lo)[i] = l.u;
}

// ---------------- Kernel B: HMMA bf16-split GEMM (3-stage ring) ------------
__global__ __launch_bounds__(256, 1) void gemm_kernel(
    const float* __restrict__ bi, const float* __restrict__ bf_,
    const float* __restrict__ bz, const float* __restrict__ bo)
{
    extern __shared__ __align__(1024) char smem[];
    const uint32_t sbase = smem_u32(smem);
    const int tid  = threadIdx.x;
    const int wid  = tid >> 5;
    const int lane = tid & 31;

    const int g  = blockIdx.z >> 2;
    const int nh = blockIdx.z & 3;
    const int m0 = blockIdx.y * BM;
    const int n0 = blockIdx.x * BN;

    const bf16* aHi0 = (g < 2 ? g_xact_hi : g_xn_hi);
    const bf16* aLo0 = (g < 2 ? g_xact_lo : g_xn_lo);
    const size_t wb0 = ((size_t)g)       * NHEAD * HSZ * HSZ + (size_t)nh * HSZ * HSZ;
    const size_t wb1 = ((size_t)(g + 4)) * NHEAD * HSZ * HSZ + (size_t)nh * HSZ * HSZ;

    // loader: 16 cp16 per thread per chunk. idx -> (row, 16B sector of 128B row)
    auto load_chunk = [&](int c) {
        const int pass = c >> 4;
        const int kt   = (c & 15) * BK;
        const uint32_t st = sbase + (uint32_t)(c % NSTAGE) * STAGE_B;
        const bf16* aH = (pass ? g_rec_hi : aHi0);
        const bf16* aL = (pass ? g_rec_lo : aLo0);
        const bf16* wH = g_w_hi + (pass ? wb1 : wb0);
        const bf16* wL = g_w_lo + (pass ? wb1 : wb0);
#pragma unroll
        for (int t = 0; t < 4; t++) {
            const int idx = tid + t * 256;          // 0..1023
            const int row = idx >> 3;
            const int sec = idx & 7;
            const uint32_t sdst = st + (uint32_t)row * TSTRIDE + sec * 16;
            const size_t aoff = (size_t)(m0 + row) * HDIM + (size_t)nh * HSZ + kt + sec * 8;
            const size_t boff = (size_t)(n0 + row) * HSZ + kt + sec * 8;
            cp16(sdst,              aH + aoff);
            cp16(sdst + TILE_B,     aL + aoff);
            cp16(sdst + 2 * TILE_B, wH + boff);
            cp16(sdst + 3 * TILE_B, wL + boff);
        }
    };

    // warp tiling: 4 warps along M (32 rows), 2 along N (64 cols)
    const int wm = wid & 3;
    const int wn = wid >> 2;

    const uint32_t aRowOff = (uint32_t)(wm * 32 + (lane & 15)) * TSTRIDE + ((lane >> 4) << 4);
    const uint32_t bRowOff = (uint32_t)(wn * 64 + (lane & 7) + ((lane >> 4) << 3)) * TSTRIDE
                             + (((lane >> 3) & 1) << 4);

    float acc[2][8][4];
#pragma unroll
    for (int mi = 0; mi < 2; mi++)
#pragma unroll
        for (int j = 0; j < 8; j++)
#pragma unroll
            for (int q = 0; q < 4; q++) acc[mi][j][q] = 0.f;

    load_chunk(0);
    asm volatile("cp.async.commit_group;");
    load_chunk(1);
    asm volatile("cp.async.commit_group;");

#pragma unroll 1
    for (int c = 0; c < NCHUNK; c++) {
        asm volatile("cp.async.wait_group 1;");
        __syncthreads();                     // chunk c visible to all; compute c-1 done

        if (c + 2 < NCHUNK) load_chunk(c + 2);
        asm volatile("cp.async.commit_group;");

        const uint32_t st = sbase + (uint32_t)(c % NSTAGE) * STAGE_B;
#pragma unroll
        for (int kk = 0; kk < 4; kk++) {
            uint32_t ah[2][4], al[2][4];
            const uint32_t ka = st + aRowOff + kk * 32;
            ldsm4(ah[0], ka);
            ldsm4(ah[1], ka + 16 * TSTRIDE);
            ldsm4(al[0], ka + TILE_B);
            ldsm4(al[1], ka + TILE_B + 16 * TSTRIDE);

            uint32_t Bh[4][4], Bl[4][4];
#pragma unroll
            for (int jj = 0; jj < 4; jj++) {
                const uint32_t kb = st + 2 * TILE_B + bRowOff + jj * 16 * TSTRIDE + kk * 32;
                ldsm4(Bh[jj], kb);
                ldsm4(Bl[jj], kb + TILE_B);
            }
            // term hi*hi
#pragma unroll
            for (int jj = 0; jj < 4; jj++) {
#pragma unroll
                for (int mi = 0; mi < 2; mi++) {
                    mma_bf16(acc[mi][2 * jj],     ah[mi], Bh[jj][0], Bh[jj][1]);
                    mma_bf16(acc[mi][2 * jj + 1], ah[mi], Bh[jj][2], Bh[jj][3]);
                }
            }
            // term hi*lo
#pragma unroll
            for (int jj = 0; jj < 4; jj++) {
#pragma unroll
                for (int mi = 0; mi < 2; mi++) {
                    mma_bf16(acc[mi][2 * jj],     ah[mi], Bl[jj][0], Bl[jj][1]);
                    mma_bf16(acc[mi][2 * jj + 1], ah[mi], Bl[jj][2], Bl[jj][3]);
                }
            }
            // term lo*hi
#pragma unroll
            for (int jj = 0; jj < 4; jj++) {
#pragma unroll
                for (int mi = 0; mi < 2; mi++) {
                    mma_bf16(acc[mi][2 * jj],     al[mi], Bh[jj][0], Bh[jj][1]);
                    mma_bf16(acc[mi][2 * jj + 1], al[mi], Bh[jj][2], Bh[jj][3]);
                }
            }
        }
    }

    // epilogue: add bias, write gates
    const float* bias = (g == 0) ? bi : (g == 1) ? bf_ : (g == 2) ? bz : bo;
    float* gbase = g_gates + (size_t)g * BATCH * HDIM;

#pragma unroll
    for (int mi = 0; mi < 2; mi++) {
        const int row0 = m0 + wm * 32 + mi * 16 + (lane >> 2);
#pragma unroll
        for (int j = 0; j < 8; j++) {
            const int col = n0 + wn * 64 + j * 8 + (lane & 3) * 2;
            const int h   = nh * HSZ + col;
            const float b0 = bias[h], b1 = bias[h + 1];
            float* p0 = gbase + (size_t)row0 * HDIM + h;
            float* p1 = p0 + 8 * HDIM;
            *(float2*)p0 = make_float2(acc[mi][j][0] + b0, acc[mi][j][1] + b1);
            *(float2*)p1 = make_float2(acc[mi][j][2] + b0, acc[mi][j][3] + b1);
        }
    }
}

// ---------------- Kernel C: gate math + group norm + outputs ---------------
__global__ __launch_bounds__(256) void gate_kernel(
    const float* __restrict__ x,      const float* __restrict__ cell,
    const float* __restrict__ normst, const float* __restrict__ maxst,
    const float* __restrict__ gn_w,   const float* __restrict__ gn_b,
    float* __restrict__ dout)
{
    const int blk = blockIdx.x;
    const int b = blk >> 2, n = blk & 3;
    const int tid = threadIdx.x;
    const size_t BH = (size_t)BATCH * HDIM;
    const size_t base = (size_t)b * HDIM + n * HSZ;
    const int c = tid * 4;

    float4 t;
    float iv[4], fv[4], zv[4], ov[4], cv[4], nv[4], mv[4];
    t = *(const float4*)(g_gates + 0 * BH + base + c); iv[0]=t.x; iv[1]=t.y; iv[2]=t.z; iv[3]=t.w;
    t = *(const float4*)(g_gates + 1 * BH + base + c); fv[0]=t.x; fv[1]=t.y; fv[2]=t.z; fv[3]=t.w;
    t = *(const float4*)(g_gates + 2 * BH + base + c); zv[0]=t.x; zv[1]=t.y; zv[2]=t.z; zv[3]=t.w;
    t = *(const float4*)(g_gates + 3 * BH + base + c); ov[0]=t.x; ov[1]=t.y; ov[2]=t.z; ov[3]=t.w;
    t = *(const float4*)(cell   + base + c); cv[0]=t.x; cv[1]=t.y; cv[2]=t.z; cv[3]=t.w;
    t = *(const float4*)(normst + base + c); nv[0]=t.x; nv[1]=t.y; nv[2]=t.z; nv[3]=t.w;
    t = *(const float4*)(maxst  + base + c); mv[0]=t.x; mv[1]=t.y; mv[2]=t.z; mv[3]=t.w;

    float y[4], cn[4], nn[4], mn[4];
    float s = 0.f, sq = 0.f;
#pragma unroll
    for (int j = 0; j < 4; ++j) {
        float fj  = fv[j];
        float lsf = fminf(fj, 0.f) - log1pf(expf(-fabsf(fj)));
        float lfm = mv[j] + lsf;
        float ij  = iv[j];
        float mnew = fmaxf(ij, lfm);
        float ig = expf(ij  - mnew);
        float fg = expf(lfm - mnew);
        float cnew = fg * cv[j] + ig * tanhf(zv[j]);
        float nnew = fg * nv[j] + ig;
        float so   = 1.f / (1.f + expf(-ov[j]));
        float yj   = so * cnew / (nnew + 1e-6f);
        y[j] = yj; cn[j] = cnew; nn[j] = nnew; mn[j] = mnew;
        s += yj; sq += yj * yj;
    }

    __shared__ float rs[8], rq[8];
    float ws = warpSum(s), wq = warpSum(sq);
    if ((tid & 31) == 0) { rs[tid >> 5] = ws; rq[tid >> 5] = wq; }
    __syncthreads();
    float ts = 0.f, tq = 0.f;
#pragma unroll
    for (int i = 0; i < 8; i++) { ts += rs[i]; tq += rq[i]; }
    const float mean = ts * (1.f / HSZ);
    const float var  = tq * (1.f / HSZ) - mean * mean;
    const float rstd = rsqrtf(var + 1e-5f);

    const int h = n * HSZ + c;
    float4 gw = *(const float4*)(gn_w + h);
    float4 gb = *(const float4*)(gn_b + h);
    float4 xs = *(const float4*)(x + base + c);
    const float gwv[4] = { gw.x, gw.y, gw.z, gw.w };
    const float gbv[4] = { gb.x, gb.y, gb.z, gb.w };
    const float xv4[4] = { xs.x, xs.y, xs.z, xs.w };

    float ot[4];
#pragma unroll
    for (int j = 0; j < 4; ++j)
        ot[j] = (y[j] - mean) * rstd * gwv[j] + gbv[j] + xv4[j];

    *(float4*)(dout + 0 * BH + base + c) = make_float4(ot[0], ot[1], ot[2], ot[3]);
    *(float4*)(dout + 4 * BH + base + c) = make_float4(y[0],  y[1],  y[2],  y[3]);
    *(float4*)(dout + 5 * BH + base + c) = make_float4(cn[0], cn[1], cn[2], cn[3]);
    *(float4*)(dout + 6 * BH + base + c) = make_float4(nn[0], nn[1], nn[2], nn[3]);
    *(float4*)(dout + 7 * BH + base + c) = make_float4(mn[0], mn[1], mn[2], mn[3]);
}

// ---------------- launch -----------------------------------------------------
extern "C" void kernel_launch(void* const* d_in, const int* in_sizes, int n_in,
                              void* d_out, int out_size)
{
    const float* x      = (const float*)d_in[0];
    const float* cs     = (const float*)d_in[1];
    const float* rec    = (const float*)d_in[2];
    const float* cell   = (const float*)d_in[3];
    const float* normst = (const float*)d_in[4];
    const float* maxst  = (const float*)d_in[5];
    const float* ln_w   = (const float*)d_in[6];
    const float* conv_w = (const float*)d_in[7];
    const float* conv_b = (const float*)d_in[8];
    const float* wi_in  = (const float*)d_in[9];
    const float* wf_in  = (const float*)d_in[10];
    const float* wz_in  = (const float*)d_in[11];
    const float* wo_in  = (const float*)d_in[12];
    const float* wi_st  = (const float*)d_in[13];
    const float* wf_st  = (const float*)d_in[14];
    const float* wz_st  = (const float*)d_in[15];
    const float* wo_st  = (const float*)d_in[16];
    const float* bi     = (const float*)d_in[17];
    const float* bf_    = (const float*)d_in[18];
    const float* bz     = (const float*)d_in[19];
    const float* bo     = (const float*)d_in[20];
    const float* gn_w   = (const float*)d_in[21];
    const float* gn_b   = (const float*)d_in[22];
    float* out = (float*)d_out;

    static int smem_set = 0;
    if (!smem_set) {
        cudaFuncSetAttribute(gemm_kernel, cudaFuncAttributeMaxDynamicSharedMemorySize,
                             SMEM_B);
        smem_set = 1;
    }

    ln_conv_kernel<<<BATCH, 256>>>(x, cs, ln_w, conv_w, conv_b,
                                   out + (size_t)BATCH * HDIM);

    convert_w_kernel<<<dim3(4096, 8), 256>>>(wi_in, wf_in, wz_in, wo_in,
                                             wi_st, wf_st, wz_st, wo_st);
    convert_rec_kernel<<<8192, 256>>>(rec);

    dim3 grid(HSZ / BN, BATCH / BM, 16);
    gemm_kernel<<<grid, 256, SMEM_B>>>(bi, bf_, bz, bo);

    gate_kernel<<<BATCH * NHEAD, 256>>>(x, cell, normst, maxst, gn_w, gn_b, out);
}